// round 9
// baseline (speedup 1.0000x reference)
#include <cuda_runtime.h>
#include <cuda_fp16.h>
#include <cstdint>

// ==================== problem sizes ====================
#define B_DIM 4096
#define H_DIM 2048
#define K_DIM 4096      // I + H
#define N4    8192      // 4*H

// ==================== tiling ====================
#define BM 128          // batch rows per CTA
#define BJ 64           // per-gate H columns per CTA
#define BN 256          // 4 gates * BJ
#define BK 128          // K per stage (fp16), = 2 x 64-k sub-blocks
#define STAGES 2
#define NIT (K_DIM / BK)              // 32
#define NTHREADS 256                  // 8 warps, 2x4 grid, 64x64 warp tiles

// scratch granularity (sub-block = 64 k)
#define A_SUB_QUADS 1024              // 128m x 64k fp16 = 16KB
#define B_SUB_QUADS 2048              // 64k x 256n fp16 = 32KB

// main-kernel stage = 2 sub-blocks
#define A_ST_QUADS (2 * A_SUB_QUADS)  // 32KB
#define B_ST_QUADS (2 * B_SUB_QUADS)  // 64KB
#define STG_BYTES  ((A_ST_QUADS + B_ST_QUADS) * 16)     // 98304
#define SMEM_BYTES (STAGES * STG_BYTES)                 // 196608

// scratch: fp16 pre-converted, fragment-ordered, swizzled SMEM images
__device__ uint4 g_Ap[(size_t)32 * 64 * A_SUB_QUADS];   // [m_tile][k_sub][1024] = 32MB
__device__ uint4 g_Wp[(size_t)32 * 64 * B_SUB_QUADS];   // [j_tile][k_sub][2048] = 64MB

// ==================== helpers ====================
__device__ __forceinline__ uint32_t smem_u32(const void* p) {
    uint32_t a;
    asm("{ .reg .u64 t; cvta.to.shared.u64 t, %1; cvt.u32.u64 %0, t; }" : "=r"(a) : "l"(p));
    return a;
}
#define CP16(dst, src) asm volatile("cp.async.cg.shared.global [%0], [%1], 16;" :: "r"(dst), "l"(src))
#define CP_COMMIT()    asm volatile("cp.async.commit_group;" ::: "memory")
#define CP_WAIT(n)     asm volatile("cp.async.wait_group %0;" :: "n"(n) : "memory")

#define MMA_F16(d, a, b)                                                         \
    asm volatile("mma.sync.aligned.m16n8k16.row.col.f32.f16.f16.f32 "            \
                 "{%0,%1,%2,%3}, {%4,%5,%6,%7}, {%8,%9}, {%0,%1,%2,%3};"         \
                 : "+f"((d)[0]), "+f"((d)[1]), "+f"((d)[2]), "+f"((d)[3])        \
                 : "r"((a)[0]), "r"((a)[1]), "r"((a)[2]), "r"((a)[3]),           \
                   "r"((b)[0]), "r"((b)[1]))

#define LDS128(r, addr)                                                          \
    asm volatile("ld.shared.v4.u32 {%0,%1,%2,%3}, [%4];"                         \
                 : "=r"((r)[0]), "=r"((r)[1]), "=r"((r)[2]), "=r"((r)[3]) : "r"(addr))

__device__ __forceinline__ uint32_t h2u(__half2 v) { return *(uint32_t*)&v; }

// ==================== prepass: A = [x|h] -> fp16 fragment quads ====================
// quad (m2, k2): m2 in [0,64), k2 in [0,16); stored at m2*16 + (k2 ^ ((m2&3)<<2))
__global__ __launch_bounds__(256) void prep_A(const float* __restrict__ x,
                                              const float* __restrict__ h) {
    __shared__ float t[128 * 64];     // 32KB
    const int kst = blockIdx.x;       // 64 k-sub-blocks
    const int mt  = blockIdx.y;       // 32 m tiles
    const int tid = threadIdx.x;
    const int kg0 = kst * 64;
    const float* src = (kg0 < H_DIM) ? x + (size_t)(mt * 128) * H_DIM + kg0
                                     : h + (size_t)(mt * 128) * H_DIM + (kg0 - H_DIM);
#pragma unroll
    for (int j = 0; j < 8; j++) {
        const int i = tid + 256 * j;            // float4 idx, 2048 total
        const int r = i >> 4, c4 = (i & 15) << 2;
        *(float4*)(t + r * 64 + c4) = *(const float4*)(src + (size_t)r * H_DIM + c4);
    }
    __syncthreads();
    uint4* outp = g_Ap + ((size_t)mt * 64 + kst) * A_SUB_QUADS;
#pragma unroll
    for (int j = 0; j < 4; j++) {
        const int w = tid + 256 * j;
        const int m2 = w >> 4, k2s = w & 15;
        const int k2 = k2s ^ ((m2 & 3) << 2);
        const int m  = ((m2 >> 3) << 4) + (m2 & 7);
        const int kb = ((k2 >> 2) << 4) + ((k2 & 3) << 1);
        uint4 q;
        q.x = h2u(__floats2half2_rn(t[m * 64 + kb],           t[m * 64 + kb + 1]));
        q.y = h2u(__floats2half2_rn(t[(m + 8) * 64 + kb],     t[(m + 8) * 64 + kb + 1]));
        q.z = h2u(__floats2half2_rn(t[m * 64 + kb + 8],       t[m * 64 + kb + 9]));
        q.w = h2u(__floats2half2_rn(t[(m + 8) * 64 + kb + 8], t[(m + 8) * 64 + kb + 9]));
        outp[w] = q;
    }
}

// ==================== prepass: W -> fp16 fragment quads, 4-gate interleaved ====================
// quad (k2, cn2): k2 in [0,16), cn2 in [0,128); stored at k2*128 + (cn2 ^ ((k2&3)<<1))
__global__ __launch_bounds__(256) void prep_W(const float* __restrict__ W) {
    __shared__ __half th[64 * 256];   // 32KB
    const int kst = blockIdx.x;       // 64 k-sub-blocks
    const int jt  = blockIdx.y;       // 32 j tiles
    const int tid = threadIdx.x;
#pragma unroll
    for (int j = 0; j < 16; j++) {
        const int i = tid + 256 * j;            // float4 idx, 4096 total
        const int r = i >> 6, sc4 = (i & 63) << 2;
        const int g = sc4 >> 6, jl = sc4 & 63;
        float4 v = *(const float4*)(W + (size_t)(kst * 64 + r) * N4 + g * H_DIM + jt * 64 + jl);
        __half* d = th + r * 256 + sc4;
        d[0] = __float2half_rn(v.x); d[1] = __float2half_rn(v.y);
        d[2] = __float2half_rn(v.z); d[3] = __float2half_rn(v.w);
    }
    __syncthreads();
    uint4* outp = g_Wp + ((size_t)jt * 64 + kst) * B_SUB_QUADS;
#pragma unroll
    for (int j = 0; j < 8; j++) {
        const int w = tid + 256 * j;
        const int k2 = w >> 7, cn2s = w & 127;
        const int cn2 = cn2s ^ ((k2 & 3) << 1);
        const int r0 = ((k2 >> 2) << 4) + ((k2 & 3) << 1);
        const int n  = ((cn2 >> 5) << 6) + (((cn2 >> 3) & 3) << 3) + (cn2 & 7);
        const int g  = (n >> 3) & 3;
        const int jl = ((n >> 5) << 3) | (n & 7);
        const int gc = g * 64 + jl;
        uint4 q;
        q.x = h2u(__halves2half2(th[r0 * 256 + gc],           th[(r0 + 1) * 256 + gc]));
        q.y = h2u(__halves2half2(th[(r0 + 8) * 256 + gc],     th[(r0 + 9) * 256 + gc]));
        q.z = h2u(__halves2half2(th[r0 * 256 + gc + 8],       th[(r0 + 1) * 256 + gc + 8]));
        q.w = h2u(__halves2half2(th[(r0 + 8) * 256 + gc + 8], th[(r0 + 9) * 256 + gc + 8]));
        outp[w] = q;
    }
}

extern __shared__ float smem[];

// ==================== fused GEMM + sLSTM kernel ====================
__global__ __launch_bounds__(NTHREADS, 1)
void slstm_mma(const float* __restrict__ c_in, const float* __restrict__ n_in,
               const float* __restrict__ m_in, const float* __restrict__ bias,
               float* __restrict__ out)
{
    const int tid = threadIdx.x;
    const int wid = tid >> 5, lane = tid & 31;
    const int gID = lane >> 2, tg = lane & 3;
    const int warpM = wid >> 2, warpN = wid & 3;     // 2 x 4 warp grid, 64x64 tiles
    const int mtile = blockIdx.x & 31;
    const int jt = blockIdx.x >> 5;
    const int m0 = mtile * BM, jb = jt * BJ;

    const uint32_t sbase = smem_u32(smem);

    float acc[4][8][4];
#pragma unroll
    for (int a = 0; a < 4; a++)
#pragma unroll
        for (int b = 0; b < 8; b++)
#pragma unroll
            for (int c = 0; c < 4; c++) acc[a][b][c] = 0.f;

    const uint4* srcAbase = g_Ap + (size_t)mtile * 64 * A_SUB_QUADS;   // 64 subs
    const uint4* srcBbase = g_Wp + (size_t)jt * 64 * B_SUB_QUADS;

    // prologue: full burst load of stage 0
    {
        const uint32_t ab = sbase;
        const uint4* sa = srcAbase;
#pragma unroll
        for (int i = 0; i < 8; i++) {
            const int c = tid + NTHREADS * i;
            CP16(ab + c * 16, sa + c);
        }
        const uint32_t bb = sbase + A_ST_QUADS * 16;
        const uint4* sb = srcBbase;
#pragma unroll
        for (int i = 0; i < 16; i++) {
            const int c = tid + NTHREADS * i;
            CP16(bb + c * 16, sb + c);
        }
        CP_COMMIT();
    }

    // invariant addressing (bytes, within a 64-k sub-block)
    uint32_t aoff[4];
#pragma unroll
    for (int mt = 0; mt < 4; mt++)
        aoff[mt] = (uint32_t)(((warpM * 4 + mt) * 8 + gID) * 256);   // m2 * 16 quads * 16B
    const uint32_t axr = (uint32_t)((gID & 3) << 2);
    uint32_t boffq[4];
#pragma unroll
    for (int ntp = 0; ntp < 4; ntp++)
        boffq[ntp] = (uint32_t)((((warpN * 32 + ntp * 8 + gID) ^ (tg << 1))
                                 + tg * 128) << 4);

    for (int it = 0; it < NIT; ++it) {
        CP_WAIT(0);
        __syncthreads();

        const int nx = it + 1;
        const bool donx = (nx < NIT);
        const uint32_t ab_nx = sbase + (uint32_t)((nx & 1) * STG_BYTES);
        const uint32_t bb_nx = ab_nx + A_ST_QUADS * 16;
        const uint4* sa_nx = srcAbase + (size_t)nx * A_ST_QUADS;
        const uint4* sb_nx = srcBbase + (size_t)nx * B_ST_QUADS;

        const uint32_t St = sbase + (uint32_t)((it & 1) * STG_BYTES);

#pragma unroll
        for (int ks = 0; ks < 8; ks++) {
            const int sub = ks >> 2, ksl = ks & 3;
            const uint32_t As = St + (uint32_t)(sub * (A_SUB_QUADS * 16));
            const uint32_t Bs = St + (uint32_t)(A_ST_QUADS * 16 + sub * (B_SUB_QUADS * 16));
            const uint32_t kpart = (uint32_t)(((ksl * 4 + tg) ^ axr) << 4);
            uint32_t ar[4][4];
#pragma unroll
            for (int mt = 0; mt < 4; mt++)
                LDS128(ar[mt], As + aoff[mt] + kpart);
            uint32_t br[8][2];
#pragma unroll
            for (int ntp = 0; ntp < 4; ntp++) {
                uint32_t t4[4];
                LDS128(t4, Bs + (uint32_t)(ksl * 8192) + boffq[ntp]);
                br[ntp][0]     = t4[0];
                br[ntp][1]     = t4[1];
                br[ntp + 4][0] = t4[2];
                br[ntp + 4][1] = t4[3];
            }

            // interleaved next-stage copy: 3 chunks per ks (24 total = 8 A + 16 B)
#pragma unroll
            for (int i = 0; i < 3; i++) {
                const int u = ks * 3 + i;                   // compile-time constant
                if (donx) {
                    if (u < 8) {
                        const int c = tid + NTHREADS * u;
                        CP16(ab_nx + c * 16, sa_nx + c);
                    } else {
                        const int c = tid + NTHREADS * (u - 8);
                        CP16(bb_nx + c * 16, sb_nx + c);
                    }
                }
            }

#pragma unroll
            for (int mt = 0; mt < 4; mt++)
#pragma unroll
                for (int nt = 0; nt < 8; nt++)
                    MMA_F16(acc[mt][nt], ar[mt], br[nt]);
        }
        CP_COMMIT();
    }

    // ---- fused sLSTM epilogue ----
    const size_t plane = (size_t)B_DIM * H_DIM;

    float bz[2][2], bi[2][2], bfv[2][2], bo[2][2];
#pragma unroll
    for (int q = 0; q < 2; q++) {
        const int j = jb + (2 * warpN + q) * 8 + 2 * tg;
#pragma unroll
        for (int e = 0; e < 2; e++) {
            bz[q][e]  = bias[j + e];
            bi[q][e]  = bias[H_DIM + j + e];
            bfv[q][e] = bias[2 * H_DIM + j + e];
            bo[q][e]  = bias[3 * H_DIM + j + e];
        }
    }

#pragma unroll
    for (int mt = 0; mt < 4; mt++) {
#pragma unroll
        for (int r2 = 0; r2 < 2; r2++) {
            const int m = m0 + warpM * 64 + mt * 16 + gID + 8 * r2;
#pragma unroll
            for (int q = 0; q < 2; q++) {
                const int j = jb + (2 * warpN + q) * 8 + 2 * tg;
                const size_t off = (size_t)m * H_DIM + j;
                const float2 cv = *(const float2*)(c_in + off);
                const float2 nv = *(const float2*)(n_in + off);
                const float2 mv = *(const float2*)(m_in + off);
                float2 ho, co, no, mo;
#pragma unroll
                for (int e = 0; e < 2; e++) {
                    const float zt  = acc[mt][q * 4 + 0][r2 * 2 + e] + bz[q][e];
                    const float it_ = acc[mt][q * 4 + 1][r2 * 2 + e] + bi[q][e];
                    const float ft  = acc[mt][q * 4 + 2][r2 * 2 + e] + bfv[q][e];
                    const float ot  = acc[mt][q * 4 + 3][r2 * 2 + e] + bo[q][e];

                    const float zv = tanhf(zt);
                    const float ef = __expf(-fabsf(ft));
                    const float rf = 1.f / (1.f + ef);
                    const float sf = (ft >= 0.f) ? rf : ef * rf;        // sigmoid(f)
                    const float logsig = fminf(ft, 0.f) - log1pf(ef);   // log sigmoid(f)
                    const float eo = __expf(-fabsf(ot));
                    const float ro = 1.f / (1.f + eo);
                    const float so = (ot >= 0.f) ? ro : eo * ro;        // sigmoid(o)

                    const float m_old = e ? mv.y : mv.x;
                    const float mt_ = fmaxf(logsig + m_old, it_);
                    const float ip = __expf(it_ - mt_);
                    const float ct = sf * (e ? cv.y : cv.x) + ip * zv;
                    const float ntv = sf * (e ? nv.y : nv.x) + ip;
                    const float htv = so * (ct / ntv);

                    *(e ? &ho.y : &ho.x) = htv;
                    *(e ? &co.y : &co.x) = ct;
                    *(e ? &no.y : &no.x) = ntv;
                    *(e ? &mo.y : &mo.x) = mt_;
                }
                *(float2*)(out + off)             = ho;
                *(float2*)(out + plane + off)     = co;
                *(float2*)(out + 2 * plane + off) = no;
                *(float2*)(out + 3 * plane + off) = mo;
            }
        }
    }
}

// ==================== host launch ====================
extern "C" void kernel_launch(void* const* d_in, const int* in_sizes, int n_in,
                              void* d_out, int out_size) {
    (void)in_sizes; (void)n_in; (void)out_size;
    const float* x    = (const float*)d_in[0];
    const float* h    = (const float*)d_in[1];
    const float* c    = (const float*)d_in[2];
    const float* n    = (const float*)d_in[3];
    const float* m    = (const float*)d_in[4];
    const float* W    = (const float*)d_in[5];
    const float* bias = (const float*)d_in[6];
    float* out = (float*)d_out;

    prep_A<<<dim3(64, 32), 256>>>(x, h);
    prep_W<<<dim3(64, 32), 256>>>(W);

    cudaFuncSetAttribute(slstm_mma, cudaFuncAttributeMaxDynamicSharedMemorySize, SMEM_BYTES);
    slstm_mma<<<(B_DIM / BM) * (H_DIM / BJ), NTHREADS, SMEM_BYTES>>>(c, n, m, bias, out);
}

// round 10
// speedup vs baseline: 1.0298x; 1.0298x over previous
#include <cuda_runtime.h>
#include <cuda_fp16.h>
#include <cstdint>

// ==================== problem sizes ====================
#define B_DIM 4096
#define H_DIM 2048
#define K_DIM 4096      // I + H
#define N4    8192      // 4*H

// ==================== tiling ====================
#define BM 128          // batch rows per CTA
#define BJ 64           // per-gate H columns per CTA
#define BN 256          // 4 gates * BJ
#define BK 128          // K per stage (fp16), = 2 x 64-k sub-blocks
#define STAGES 2
#define NIT (K_DIM / BK)              // 32
#define NTHREADS 256                  // 8 warps, 2x4 grid, 64x64 warp tiles

// scratch granularity (sub-block = 64 k)
#define A_SUB_QUADS 1024              // 128m x 64k fp16 = 16KB
#define B_SUB_QUADS 2048              // 64k x 256n fp16 = 32KB

// main-kernel stage = 2 sub-blocks
#define A_ST_QUADS (2 * A_SUB_QUADS)  // 32KB
#define B_ST_QUADS (2 * B_SUB_QUADS)  // 64KB
#define STG_BYTES  ((A_ST_QUADS + B_ST_QUADS) * 16)     // 98304
#define SMEM_BYTES (STAGES * STG_BYTES)                 // 196608

// scratch: fp16 pre-converted, fragment-ordered, swizzled SMEM images
__device__ uint4 g_Ap[(size_t)32 * 64 * A_SUB_QUADS];   // [m_tile][k_sub][1024] = 32MB
__device__ uint4 g_Wp[(size_t)32 * 64 * B_SUB_QUADS];   // [j_tile][k_sub][2048] = 64MB

// ==================== helpers ====================
__device__ __forceinline__ uint32_t smem_u32(const void* p) {
    uint32_t a;
    asm("{ .reg .u64 t; cvta.to.shared.u64 t, %1; cvt.u32.u64 %0, t; }" : "=r"(a) : "l"(p));
    return a;
}
#define CP16(dst, src) asm volatile("cp.async.cg.shared.global [%0], [%1], 16;" :: "r"(dst), "l"(src))
#define CP_COMMIT()    asm volatile("cp.async.commit_group;" ::: "memory")
#define CP_WAIT(n)     asm volatile("cp.async.wait_group %0;" :: "n"(n) : "memory")

#define MMA_F16(d, a, b)                                                         \
    asm volatile("mma.sync.aligned.m16n8k16.row.col.f32.f16.f16.f32 "            \
                 "{%0,%1,%2,%3}, {%4,%5,%6,%7}, {%8,%9}, {%0,%1,%2,%3};"         \
                 : "+f"((d)[0]), "+f"((d)[1]), "+f"((d)[2]), "+f"((d)[3])        \
                 : "r"((a)[0]), "r"((a)[1]), "r"((a)[2]), "r"((a)[3]),           \
                   "r"((b)[0]), "r"((b)[1]))

#define LDS128(r, addr)                                                          \
    asm volatile("ld.shared.v4.u32 {%0,%1,%2,%3}, [%4];"                         \
                 : "=r"((r)[0]), "=r"((r)[1]), "=r"((r)[2]), "=r"((r)[3]) : "r"(addr))

__device__ __forceinline__ uint32_t h2u(__half2 v) { return *(uint32_t*)&v; }

// ==================== prepass: A = [x|h] -> fp16 fragment quads ====================
// quad (m2, k2): m2 in [0,64), k2 in [0,16); stored at m2*16 + (k2 ^ ((m2&3)<<2))
__global__ __launch_bounds__(256) void prep_A(const float* __restrict__ x,
                                              const float* __restrict__ h) {
    __shared__ float t[128 * 64];     // 32KB
    const int kst = blockIdx.x;       // 64 k-sub-blocks
    const int mt  = blockIdx.y;       // 32 m tiles
    const int tid = threadIdx.x;
    const int kg0 = kst * 64;
    const float* src = (kg0 < H_DIM) ? x + (size_t)(mt * 128) * H_DIM + kg0
                                     : h + (size_t)(mt * 128) * H_DIM + (kg0 - H_DIM);
#pragma unroll
    for (int j = 0; j < 8; j++) {
        const int i = tid + 256 * j;            // float4 idx, 2048 total
        const int r = i >> 4, c4 = (i & 15) << 2;
        *(float4*)(t + r * 64 + c4) = *(const float4*)(src + (size_t)r * H_DIM + c4);
    }
    __syncthreads();
    uint4* outp = g_Ap + ((size_t)mt * 64 + kst) * A_SUB_QUADS;
#pragma unroll
    for (int j = 0; j < 4; j++) {
        const int w = tid + 256 * j;
        const int m2 = w >> 4, k2s = w & 15;
        const int k2 = k2s ^ ((m2 & 3) << 2);
        const int m  = ((m2 >> 3) << 4) + (m2 & 7);
        const int kb = ((k2 >> 2) << 4) + ((k2 & 3) << 1);
        uint4 q;
        q.x = h2u(__floats2half2_rn(t[m * 64 + kb],           t[m * 64 + kb + 1]));
        q.y = h2u(__floats2half2_rn(t[(m + 8) * 64 + kb],     t[(m + 8) * 64 + kb + 1]));
        q.z = h2u(__floats2half2_rn(t[m * 64 + kb + 8],       t[m * 64 + kb + 9]));
        q.w = h2u(__floats2half2_rn(t[(m + 8) * 64 + kb + 8], t[(m + 8) * 64 + kb + 9]));
        outp[w] = q;
    }
}

// ==================== prepass: W -> fp16 fragment quads, 4-gate interleaved ====================
// quad (k2, cn2): k2 in [0,16), cn2 in [0,128); stored at k2*128 + (cn2 ^ ((k2&3)<<1))
__global__ __launch_bounds__(256) void prep_W(const float* __restrict__ W) {
    __shared__ __half th[64 * 256];   // 32KB
    const int kst = blockIdx.x;       // 64 k-sub-blocks
    const int jt  = blockIdx.y;       // 32 j tiles
    const int tid = threadIdx.x;
#pragma unroll
    for (int j = 0; j < 16; j++) {
        const int i = tid + 256 * j;            // float4 idx, 4096 total
        const int r = i >> 6, sc4 = (i & 63) << 2;
        const int g = sc4 >> 6, jl = sc4 & 63;
        float4 v = *(const float4*)(W + (size_t)(kst * 64 + r) * N4 + g * H_DIM + jt * 64 + jl);
        __half* d = th + r * 256 + sc4;
        d[0] = __float2half_rn(v.x); d[1] = __float2half_rn(v.y);
        d[2] = __float2half_rn(v.z); d[3] = __float2half_rn(v.w);
    }
    __syncthreads();
    uint4* outp = g_Wp + ((size_t)jt * 64 + kst) * B_SUB_QUADS;
#pragma unroll
    for (int j = 0; j < 8; j++) {
        const int w = tid + 256 * j;
        const int k2 = w >> 7, cn2s = w & 127;
        const int cn2 = cn2s ^ ((k2 & 3) << 1);
        const int r0 = ((k2 >> 2) << 4) + ((k2 & 3) << 1);
        const int n  = ((cn2 >> 5) << 6) + (((cn2 >> 3) & 3) << 3) + (cn2 & 7);
        const int g  = (n >> 3) & 3;
        const int jl = ((n >> 5) << 3) | (n & 7);
        const int gc = g * 64 + jl;
        uint4 q;
        q.x = h2u(__halves2half2(th[r0 * 256 + gc],           th[(r0 + 1) * 256 + gc]));
        q.y = h2u(__halves2half2(th[(r0 + 8) * 256 + gc],     th[(r0 + 9) * 256 + gc]));
        q.z = h2u(__halves2half2(th[r0 * 256 + gc + 8],       th[(r0 + 1) * 256 + gc + 8]));
        q.w = h2u(__halves2half2(th[(r0 + 8) * 256 + gc + 8], th[(r0 + 9) * 256 + gc + 8]));
        outp[w] = q;
    }
}

extern __shared__ float smem[];

// ==================== fused GEMM + sLSTM kernel ====================
__global__ __launch_bounds__(NTHREADS, 1)
void slstm_mma(const float* __restrict__ c_in, const float* __restrict__ n_in,
               const float* __restrict__ m_in, const float* __restrict__ bias,
               float* __restrict__ out)
{
    const int tid = threadIdx.x;
    const int wid = tid >> 5, lane = tid & 31;
    const int gID = lane >> 2, tg = lane & 3;
    const int warpM = wid >> 2, warpN = wid & 3;     // 2 x 4 warp grid, 64x64 tiles
    const int mtile = blockIdx.x & 31;
    const int jt = blockIdx.x >> 5;
    const int m0 = mtile * BM, jb = jt * BJ;

    const uint32_t sbase = smem_u32(smem);

    float acc[4][8][4];
#pragma unroll
    for (int a = 0; a < 4; a++)
#pragma unroll
        for (int b = 0; b < 8; b++)
#pragma unroll
            for (int c = 0; c < 4; c++) acc[a][b][c] = 0.f;

    const uint4* srcAbase = g_Ap + (size_t)mtile * 64 * A_SUB_QUADS;   // 64 subs
    const uint4* srcBbase = g_Wp + (size_t)jt * 64 * B_SUB_QUADS;

    // stage s (BK=128) = subs {2s, 2s+1} laid out consecutively in scratch
    auto load_stage = [&](int slot, int s) {
        const uint32_t ab = sbase + (uint32_t)(slot * STG_BYTES);
        const uint4* sa = srcAbase + (size_t)s * A_ST_QUADS;
#pragma unroll
        for (int i = 0; i < 8; i++) {
            const int c = tid + NTHREADS * i;
            CP16(ab + c * 16, sa + c);
        }
        const uint32_t bb = ab + A_ST_QUADS * 16;
        const uint4* sb = srcBbase + (size_t)s * B_ST_QUADS;
#pragma unroll
        for (int i = 0; i < 16; i++) {
            const int c = tid + NTHREADS * i;
            CP16(bb + c * 16, sb + c);
        }
    };

    load_stage(0, 0);
    CP_COMMIT();

    // invariant addressing (bytes, within a 64-k sub-block)
    uint32_t aoff[4];
#pragma unroll
    for (int mt = 0; mt < 4; mt++)
        aoff[mt] = (uint32_t)(((warpM * 4 + mt) * 8 + gID) * 256);   // m2 * 16 quads * 16B
    const uint32_t axr = (uint32_t)((gID & 3) << 2);
    uint32_t boffq[4];
#pragma unroll
    for (int ntp = 0; ntp < 4; ntp++)
        boffq[ntp] = (uint32_t)((((warpN * 32 + ntp * 8 + gID) ^ (tg << 1))
                                 + tg * 128) << 4);

    // double-buffered fragments
    uint32_t ar[2][4][4];
    uint32_t br[2][8][2];

    // fragment loader for step ks of the stage at SMEM base St
    auto frag_load = [&](uint32_t St, int ks, int buf) {
        const int sub = ks >> 2, ksl = ks & 3;
        const uint32_t As = St + (uint32_t)(sub * (A_SUB_QUADS * 16));
        const uint32_t Bs = St + (uint32_t)(A_ST_QUADS * 16 + sub * (B_SUB_QUADS * 16));
        const uint32_t kpart = (uint32_t)(((ksl * 4 + tg) ^ axr) << 4);
#pragma unroll
        for (int mt = 0; mt < 4; mt++)
            LDS128(ar[buf][mt], As + aoff[mt] + kpart);
#pragma unroll
        for (int ntp = 0; ntp < 4; ntp++) {
            uint32_t t4[4];
            LDS128(t4, Bs + (uint32_t)(ksl * 8192) + boffq[ntp]);
            br[buf][ntp][0]     = t4[0];
            br[buf][ntp][1]     = t4[1];
            br[buf][ntp + 4][0] = t4[2];
            br[buf][ntp + 4][1] = t4[3];
        }
    };

    for (int it = 0; it < NIT; ++it) {
        CP_WAIT(0);
        __syncthreads();

        const int nx = it + 1;
        if (nx < NIT) load_stage(nx & 1, nx);
        CP_COMMIT();

        const uint32_t St = sbase + (uint32_t)((it & 1) * STG_BYTES);

        frag_load(St, 0, 0);
#pragma unroll
        for (int ks = 0; ks < 8; ks++) {
            const int cur = ks & 1;
            if (ks < 7) frag_load(St, ks + 1, cur ^ 1);
#pragma unroll
            for (int mt = 0; mt < 4; mt++)
#pragma unroll
                for (int nt = 0; nt < 8; nt++)
                    MMA_F16(acc[mt][nt], ar[cur][mt], br[cur][nt]);
        }
    }

    // ---- fused sLSTM epilogue ----
    const size_t plane = (size_t)B_DIM * H_DIM;

    float bz[2][2], bi[2][2], bfv[2][2], bo[2][2];
#pragma unroll
    for (int q = 0; q < 2; q++) {
        const int j = jb + (2 * warpN + q) * 8 + 2 * tg;
#pragma unroll
        for (int e = 0; e < 2; e++) {
            bz[q][e]  = bias[j + e];
            bi[q][e]  = bias[H_DIM + j + e];
            bfv[q][e] = bias[2 * H_DIM + j + e];
            bo[q][e]  = bias[3 * H_DIM + j + e];
        }
    }

#pragma unroll
    for (int mt = 0; mt < 4; mt++) {
#pragma unroll
        for (int r2 = 0; r2 < 2; r2++) {
            const int m = m0 + warpM * 64 + mt * 16 + gID + 8 * r2;
#pragma unroll
            for (int q = 0; q < 2; q++) {
                const int j = jb + (2 * warpN + q) * 8 + 2 * tg;
                const size_t off = (size_t)m * H_DIM + j;
                const float2 cv = *(const float2*)(c_in + off);
                const float2 nv = *(const float2*)(n_in + off);
                const float2 mv = *(const float2*)(m_in + off);
                float2 ho, co, no, mo;
#pragma unroll
                for (int e = 0; e < 2; e++) {
                    const float zt  = acc[mt][q * 4 + 0][r2 * 2 + e] + bz[q][e];
                    const float it_ = acc[mt][q * 4 + 1][r2 * 2 + e] + bi[q][e];
                    const float ft  = acc[mt][q * 4 + 2][r2 * 2 + e] + bfv[q][e];
                    const float ot  = acc[mt][q * 4 + 3][r2 * 2 + e] + bo[q][e];

                    const float zv = tanhf(zt);
                    const float ef = __expf(-fabsf(ft));
                    const float rf = 1.f / (1.f + ef);
                    const float sf = (ft >= 0.f) ? rf : ef * rf;        // sigmoid(f)
                    const float logsig = fminf(ft, 0.f) - log1pf(ef);   // log sigmoid(f)
                    const float eo = __expf(-fabsf(ot));
                    const float ro = 1.f / (1.f + eo);
                    const float so = (ot >= 0.f) ? ro : eo * ro;        // sigmoid(o)

                    const float m_old = e ? mv.y : mv.x;
                    const float mt_ = fmaxf(logsig + m_old, it_);
                    const float ip = __expf(it_ - mt_);
                    const float ct = sf * (e ? cv.y : cv.x) + ip * zv;
                    const float ntv = sf * (e ? nv.y : nv.x) + ip;
                    const float htv = so * (ct / ntv);

                    *(e ? &ho.y : &ho.x) = htv;
                    *(e ? &co.y : &co.x) = ct;
                    *(e ? &no.y : &no.x) = ntv;
                    *(e ? &mo.y : &mo.x) = mt_;
                }
                *(float2*)(out + off)             = ho;
                *(float2*)(out + plane + off)     = co;
                *(float2*)(out + 2 * plane + off) = no;
                *(float2*)(out + 3 * plane + off) = mo;
            }
        }
    }
}

// ==================== host launch ====================
extern "C" void kernel_launch(void* const* d_in, const int* in_sizes, int n_in,
                              void* d_out, int out_size) {
    (void)in_sizes; (void)n_in; (void)out_size;
    const float* x    = (const float*)d_in[0];
    const float* h    = (const float*)d_in[1];
    const float* c    = (const float*)d_in[2];
    const float* n    = (const float*)d_in[3];
    const float* m    = (const float*)d_in[4];
    const float* W    = (const float*)d_in[5];
    const float* bias = (const float*)d_in[6];
    float* out = (float*)d_out;

    prep_A<<<dim3(64, 32), 256>>>(x, h);
    prep_W<<<dim3(64, 32), 256>>>(W);

    cudaFuncSetAttribute(slstm_mma, cudaFuncAttributeMaxDynamicSharedMemorySize, SMEM_BYTES);
    slstm_mma<<<(B_DIM / BM) * (H_DIM / BJ), NTHREADS, SMEM_BYTES>>>(c, n, m, bias, out);
}

// round 11
// speedup vs baseline: 1.0738x; 1.0427x over previous
#include <cuda_runtime.h>
#include <cuda_fp16.h>
#include <cstdint>

// ==================== problem sizes ====================
#define B_DIM 4096
#define H_DIM 2048
#define K_DIM 4096      // I + H
#define N4    8192      // 4*H

// ==================== tiling ====================
#define BM 128          // batch rows per CTA tile
#define BJ 64           // per-gate H columns per CTA tile
#define BN 256          // 4 gates * BJ
#define BK 128          // K per stage (fp16), = 2 x 64-k sub-blocks
#define NIT (K_DIM / BK)              // 32
#define NTHREADS 256                  // 8 warps, 2x4 grid, 64x64 warp tiles
#define GRID 152                      // persistent CTAs (GB300 SM count)
#define NTILES 1024                   // 32 m-tiles x 32 j-tiles

// scratch granularity (sub-block = 64 k)
#define A_SUB_QUADS 1024              // 128m x 64k fp16 = 16KB
#define B_SUB_QUADS 2048              // 64k x 256n fp16 = 32KB

// main-kernel stage = 2 sub-blocks
#define A_ST_QUADS (2 * A_SUB_QUADS)  // 32KB
#define B_ST_QUADS (2 * B_SUB_QUADS)  // 64KB
#define STG_BYTES  ((A_ST_QUADS + B_ST_QUADS) * 16)     // 98304
#define SMEM_BYTES (2 * STG_BYTES)                      // 196608

// scratch: fp16 pre-converted, fragment-ordered, swizzled SMEM images
__device__ uint4 g_Ap[(size_t)32 * 64 * A_SUB_QUADS];   // [m_tile][k_sub][1024] = 32MB
__device__ uint4 g_Wp[(size_t)32 * 64 * B_SUB_QUADS];   // [j_tile][k_sub][2048] = 64MB

// ==================== helpers ====================
__device__ __forceinline__ uint32_t smem_u32(const void* p) {
    uint32_t a;
    asm("{ .reg .u64 t; cvta.to.shared.u64 t, %1; cvt.u32.u64 %0, t; }" : "=r"(a) : "l"(p));
    return a;
}
#define CP16(dst, src) asm volatile("cp.async.cg.shared.global [%0], [%1], 16;" :: "r"(dst), "l"(src))
#define CP_COMMIT()    asm volatile("cp.async.commit_group;" ::: "memory")
#define CP_WAIT(n)     asm volatile("cp.async.wait_group %0;" :: "n"(n) : "memory")
#define PREF_L2(p)     asm volatile("prefetch.global.L2 [%0];" :: "l"(p))

#define MMA_F16(d, a, b)                                                         \
    asm volatile("mma.sync.aligned.m16n8k16.row.col.f32.f16.f16.f32 "            \
                 "{%0,%1,%2,%3}, {%4,%5,%6,%7}, {%8,%9}, {%0,%1,%2,%3};"         \
                 : "+f"((d)[0]), "+f"((d)[1]), "+f"((d)[2]), "+f"((d)[3])        \
                 : "r"((a)[0]), "r"((a)[1]), "r"((a)[2]), "r"((a)[3]),           \
                   "r"((b)[0]), "r"((b)[1]))

#define LDS128(r, addr)                                                          \
    asm volatile("ld.shared.v4.u32 {%0,%1,%2,%3}, [%4];"                         \
                 : "=r"((r)[0]), "=r"((r)[1]), "=r"((r)[2]), "=r"((r)[3]) : "r"(addr))

__device__ __forceinline__ uint32_t h2u(__half2 v) { return *(uint32_t*)&v; }

// ==================== prepass: A = [x|h] -> fp16 fragment quads ====================
// quad (m2, k2): m2 in [0,64), k2 in [0,16); stored at m2*16 + (k2 ^ ((m2&3)<<2))
__global__ __launch_bounds__(256) void prep_A(const float* __restrict__ x,
                                              const float* __restrict__ h) {
    __shared__ float t[128 * 64];     // 32KB
    const int kst = blockIdx.x;       // 64 k-sub-blocks
    const int mt  = blockIdx.y;       // 32 m tiles
    const int tid = threadIdx.x;
    const int kg0 = kst * 64;
    const float* src = (kg0 < H_DIM) ? x + (size_t)(mt * 128) * H_DIM + kg0
                                     : h + (size_t)(mt * 128) * H_DIM + (kg0 - H_DIM);
#pragma unroll
    for (int j = 0; j < 8; j++) {
        const int i = tid + 256 * j;            // float4 idx, 2048 total
        const int r = i >> 4, c4 = (i & 15) << 2;
        *(float4*)(t + r * 64 + c4) = *(const float4*)(src + (size_t)r * H_DIM + c4);
    }
    __syncthreads();
    uint4* outp = g_Ap + ((size_t)mt * 64 + kst) * A_SUB_QUADS;
#pragma unroll
    for (int j = 0; j < 4; j++) {
        const int w = tid + 256 * j;
        const int m2 = w >> 4, k2s = w & 15;
        const int k2 = k2s ^ ((m2 & 3) << 2);
        const int m  = ((m2 >> 3) << 4) + (m2 & 7);
        const int kb = ((k2 >> 2) << 4) + ((k2 & 3) << 1);
        uint4 q;
        q.x = h2u(__floats2half2_rn(t[m * 64 + kb],           t[m * 64 + kb + 1]));
        q.y = h2u(__floats2half2_rn(t[(m + 8) * 64 + kb],     t[(m + 8) * 64 + kb + 1]));
        q.z = h2u(__floats2half2_rn(t[m * 64 + kb + 8],       t[m * 64 + kb + 9]));
        q.w = h2u(__floats2half2_rn(t[(m + 8) * 64 + kb + 8], t[(m + 8) * 64 + kb + 9]));
        outp[w] = q;
    }
}

// ==================== prepass: W -> fp16 fragment quads, 4-gate interleaved ====================
// quad (k2, cn2): k2 in [0,16), cn2 in [0,128); stored at k2*128 + (cn2 ^ ((k2&3)<<1))
__global__ __launch_bounds__(256) void prep_W(const float* __restrict__ W) {
    __shared__ __half th[64 * 256];   // 32KB
    const int kst = blockIdx.x;       // 64 k-sub-blocks
    const int jt  = blockIdx.y;       // 32 j tiles
    const int tid = threadIdx.x;
#pragma unroll
    for (int j = 0; j < 16; j++) {
        const int i = tid + 256 * j;            // float4 idx, 4096 total
        const int r = i >> 6, sc4 = (i & 63) << 2;
        const int g = sc4 >> 6, jl = sc4 & 63;
        float4 v = *(const float4*)(W + (size_t)(kst * 64 + r) * N4 + g * H_DIM + jt * 64 + jl);
        __half* d = th + r * 256 + sc4;
        d[0] = __float2half_rn(v.x); d[1] = __float2half_rn(v.y);
        d[2] = __float2half_rn(v.z); d[3] = __float2half_rn(v.w);
    }
    __syncthreads();
    uint4* outp = g_Wp + ((size_t)jt * 64 + kst) * B_SUB_QUADS;
#pragma unroll
    for (int j = 0; j < 8; j++) {
        const int w = tid + 256 * j;
        const int k2 = w >> 7, cn2s = w & 127;
        const int cn2 = cn2s ^ ((k2 & 3) << 1);
        const int r0 = ((k2 >> 2) << 4) + ((k2 & 3) << 1);
        const int n  = ((cn2 >> 5) << 6) + (((cn2 >> 3) & 3) << 3) + (cn2 & 7);
        const int g  = (n >> 3) & 3;
        const int jl = ((n >> 5) << 3) | (n & 7);
        const int gc = g * 64 + jl;
        uint4 q;
        q.x = h2u(__halves2half2(th[r0 * 256 + gc],           th[(r0 + 1) * 256 + gc]));
        q.y = h2u(__halves2half2(th[(r0 + 8) * 256 + gc],     th[(r0 + 9) * 256 + gc]));
        q.z = h2u(__halves2half2(th[r0 * 256 + gc + 8],       th[(r0 + 1) * 256 + gc + 8]));
        q.w = h2u(__halves2half2(th[(r0 + 8) * 256 + gc + 8], th[(r0 + 9) * 256 + gc + 8]));
        outp[w] = q;
    }
}

extern __shared__ float smem[];

// ==================== fused GEMM + sLSTM kernel (persistent) ====================
__global__ __launch_bounds__(NTHREADS, 1)
void slstm_mma(const float* __restrict__ c_in, const float* __restrict__ n_in,
               const float* __restrict__ m_in, const float* __restrict__ bias,
               float* __restrict__ out)
{
    const int tid = threadIdx.x;
    const int wid = tid >> 5, lane = tid & 31;
    const int gID = lane >> 2, tg = lane & 3;
    const int warpM = wid >> 2, warpN = wid & 3;     // 2 x 4 warp grid, 64x64 tiles

    const uint32_t sbase = smem_u32(smem);
    const size_t plane = (size_t)B_DIM * H_DIM;

    // tile-invariant fragment addressing (bytes, within a 64-k sub-block)
    uint32_t aoff[4];
#pragma unroll
    for (int mt = 0; mt < 4; mt++)
        aoff[mt] = (uint32_t)(((warpM * 4 + mt) * 8 + gID) * 256);
    const uint32_t axr = (uint32_t)((gID & 3) << 2);
    uint32_t boffq[4];
#pragma unroll
    for (int ntp = 0; ntp < 4; ntp++)
        boffq[ntp] = (uint32_t)((((warpN * 32 + ntp * 8 + gID) ^ (tg << 1))
                                 + tg * 128) << 4);

    // stage copy: 24 x 16B chunks per thread
    auto load_stage = [&](int slot, const uint4* sa, const uint4* sb) {
        const uint32_t ab = sbase + (uint32_t)(slot * STG_BYTES);
#pragma unroll
        for (int i = 0; i < 8; i++) {
            const int c = tid + NTHREADS * i;
            CP16(ab + c * 16, sa + c);
        }
        const uint32_t bb = ab + A_ST_QUADS * 16;
#pragma unroll
        for (int i = 0; i < 16; i++) {
            const int c = tid + NTHREADS * i;
            CP16(bb + c * 16, sb + c);
        }
    };

    // double-buffered fragments
    uint32_t ar[2][4][4];
    uint32_t br[2][8][2];
    auto frag_load = [&](uint32_t St, int ks, int buf) {
        const int sub = ks >> 2, ksl = ks & 3;
        const uint32_t As = St + (uint32_t)(sub * (A_SUB_QUADS * 16));
        const uint32_t Bs = St + (uint32_t)(A_ST_QUADS * 16 + sub * (B_SUB_QUADS * 16));
        const uint32_t kpart = (uint32_t)(((ksl * 4 + tg) ^ axr) << 4);
#pragma unroll
        for (int mt = 0; mt < 4; mt++)
            LDS128(ar[buf][mt], As + aoff[mt] + kpart);
#pragma unroll
        for (int ntp = 0; ntp < 4; ntp++) {
            uint32_t t4[4];
            LDS128(t4, Bs + (uint32_t)(ksl * 8192) + boffq[ntp]);
            br[buf][ntp][0]     = t4[0];
            br[buf][ntp][1]     = t4[1];
            br[buf][ntp + 4][0] = t4[2];
            br[buf][ntp + 4][1] = t4[3];
        }
    };

    // prologue: stage 0 of first tile
    {
        const int t0 = blockIdx.x;
        load_stage(0, g_Ap + (size_t)(t0 & 31) * 64 * A_SUB_QUADS,
                      g_Wp + (size_t)(t0 >> 5) * 64 * B_SUB_QUADS);
        CP_COMMIT();
    }

    for (int tile = blockIdx.x; tile < NTILES; tile += GRID) {
        const int mtile = tile & 31;
        const int jt = tile >> 5;
        const int m0 = mtile * BM, jb = jt * BJ;
        const uint4* srcAbase = g_Ap + (size_t)mtile * 64 * A_SUB_QUADS;
        const uint4* srcBbase = g_Wp + (size_t)jt * 64 * B_SUB_QUADS;

        float acc[4][8][4];
#pragma unroll
        for (int a = 0; a < 4; a++)
#pragma unroll
            for (int b = 0; b < 8; b++)
#pragma unroll
                for (int c = 0; c < 4; c++) acc[a][b][c] = 0.f;

        for (int it = 0; it < NIT; ++it) {
            CP_WAIT(0);
            __syncthreads();

            const int nx = it + 1;
            if (nx < NIT)
                load_stage(nx & 1, srcAbase + (size_t)nx * A_ST_QUADS,
                                   srcBbase + (size_t)nx * B_ST_QUADS);
            CP_COMMIT();

            if (it == NIT - 1) {
                // prefetch epilogue state inputs to L2
#pragma unroll
                for (int mt = 0; mt < 4; mt++) {
#pragma unroll
                    for (int r2 = 0; r2 < 2; r2++) {
                        const int m = m0 + warpM * 64 + mt * 16 + gID + 8 * r2;
#pragma unroll
                        for (int q = 0; q < 2; q++) {
                            const size_t off = (size_t)m * H_DIM + jb
                                             + (2 * warpN + q) * 8 + 2 * tg;
                            PREF_L2(c_in + off);
                            PREF_L2(n_in + off);
                            PREF_L2(m_in + off);
                        }
                    }
                }
            }

            const uint32_t St = sbase + (uint32_t)((it & 1) * STG_BYTES);
            frag_load(St, 0, 0);
#pragma unroll
            for (int ks = 0; ks < 8; ks++) {
                const int cur = ks & 1;
                if (ks < 7) frag_load(St, ks + 1, cur ^ 1);
#pragma unroll
                for (int mt = 0; mt < 4; mt++)
#pragma unroll
                    for (int nt = 0; nt < 8; nt++)
                        MMA_F16(acc[mt][nt], ar[cur][mt], br[cur][nt]);
            }
        }

        // issue next tile's stage-0 copy before the epilogue (hides prologue)
        {
            const int tn = tile + GRID;
            if (tn < NTILES) {
                load_stage(0, g_Ap + (size_t)(tn & 31) * 64 * A_SUB_QUADS,
                              g_Wp + (size_t)(tn >> 5) * 64 * B_SUB_QUADS);
                CP_COMMIT();
            }
        }

        // ---- fused sLSTM epilogue (fast-math) ----
#pragma unroll
        for (int mt = 0; mt < 4; mt++) {
#pragma unroll
            for (int r2 = 0; r2 < 2; r2++) {
                const int m = m0 + warpM * 64 + mt * 16 + gID + 8 * r2;
#pragma unroll
                for (int q = 0; q < 2; q++) {
                    const int j = jb + (2 * warpN + q) * 8 + 2 * tg;
                    const size_t off = (size_t)m * H_DIM + j;
                    const float2 cv = *(const float2*)(c_in + off);
                    const float2 nv = *(const float2*)(n_in + off);
                    const float2 mv = *(const float2*)(m_in + off);
                    float2 ho, co, no, mo;
#pragma unroll
                    for (int e = 0; e < 2; e++) {
                        const float zt  = acc[mt][q * 4 + 0][r2 * 2 + e] + bias[j + e];
                        const float it_ = acc[mt][q * 4 + 1][r2 * 2 + e] + bias[H_DIM + j + e];
                        const float ft  = acc[mt][q * 4 + 2][r2 * 2 + e] + bias[2 * H_DIM + j + e];
                        const float ot  = acc[mt][q * 4 + 3][r2 * 2 + e] + bias[3 * H_DIM + j + e];

                        // tanh via exp
                        const float ez = __expf(-2.f * fabsf(zt));
                        const float tv = __fdividef(1.f - ez, 1.f + ez);
                        const float zv = (zt >= 0.f) ? tv : -tv;
                        // sigmoid(f) + log sigmoid(f)
                        const float ef = __expf(-fabsf(ft));
                        const float rf = __fdividef(1.f, 1.f + ef);
                        const float sf = (ft >= 0.f) ? rf : ef * rf;
                        const float logsig = fminf(ft, 0.f) - __logf(1.f + ef);
                        // sigmoid(o)
                        const float eo = __expf(-fabsf(ot));
                        const float ro = __fdividef(1.f, 1.f + eo);
                        const float so = (ot >= 0.f) ? ro : eo * ro;

                        const float m_old = e ? mv.y : mv.x;
                        const float mt_ = fmaxf(logsig + m_old, it_);
                        const float ip = __expf(it_ - mt_);
                        const float ct = sf * (e ? cv.y : cv.x) + ip * zv;
                        const float ntv = sf * (e ? nv.y : nv.x) + ip;
                        const float htv = so * __fdividef(ct, ntv);

                        *(e ? &ho.y : &ho.x) = htv;
                        *(e ? &co.y : &co.x) = ct;
                        *(e ? &no.y : &no.x) = ntv;
                        *(e ? &mo.y : &mo.x) = mt_;
                    }
                    *(float2*)(out + off)             = ho;
                    *(float2*)(out + plane + off)     = co;
                    *(float2*)(out + 2 * plane + off) = no;
                    *(float2*)(out + 3 * plane + off) = mo;
                }
            }
        }
    }
}

// ==================== host launch ====================
extern "C" void kernel_launch(void* const* d_in, const int* in_sizes, int n_in,
                              void* d_out, int out_size) {
    (void)in_sizes; (void)n_in; (void)out_size;
    const float* x    = (const float*)d_in[0];
    const float* h    = (const float*)d_in[1];
    const float* c    = (const float*)d_in[2];
    const float* n    = (const float*)d_in[3];
    const float* m    = (const float*)d_in[4];
    const float* W    = (const float*)d_in[5];
    const float* bias = (const float*)d_in[6];
    float* out = (float*)d_out;

    prep_A<<<dim3(64, 32), 256>>>(x, h);
    prep_W<<<dim3(64, 32), 256>>>(W);

    cudaFuncSetAttribute(slstm_mma, cudaFuncAttributeMaxDynamicSharedMemorySize, SMEM_BYTES);
    slstm_mma<<<GRID, NTHREADS, SMEM_BYTES>>>(c, n, m, bias, out);
}

// round 12
// speedup vs baseline: 1.0773x; 1.0033x over previous
#include <cuda_runtime.h>
#include <cuda_fp16.h>
#include <cstdint>

// ==================== problem sizes ====================
#define B_DIM 4096
#define H_DIM 2048
#define K_DIM 4096      // I + H
#define N4    8192      // 4*H

// ==================== tiling ====================
#define BM 128          // batch rows per CTA tile
#define BJ 64           // per-gate H columns per CTA tile
#define BN 256          // 4 gates * BJ
#define BK 128          // K per stage (fp16), = 2 x 64-k sub-blocks
#define NIT (K_DIM / BK)              // 32
#define NTHREADS 256                  // 8 warps, 2x4 grid, 64x64 warp tiles
#define GRID 152                      // persistent CTAs (GB300 SM count)
#define NTILES 1024                   // 32 m-tiles x 32 j-tiles

// scratch granularity (sub-block = 64 k)
#define A_SUB_QUADS 1024              // 128m x 64k fp16 = 16KB
#define B_SUB_QUADS 2048              // 64k x 256n fp16 = 32KB

// main-kernel stage = 2 sub-blocks
#define A_ST_QUADS (2 * A_SUB_QUADS)  // 32KB
#define B_ST_QUADS (2 * B_SUB_QUADS)  // 64KB
#define STG_BYTES  ((A_ST_QUADS + B_ST_QUADS) * 16)     // 98304
#define SMEM_BYTES (2 * STG_BYTES)                      // 196608

// scratch: fp16 pre-converted, fragment-ordered, swizzled SMEM images
__device__ uint4 g_Ap[(size_t)32 * 64 * A_SUB_QUADS];   // [m_tile][k_sub][1024] = 32MB
__device__ uint4 g_Wp[(size_t)32 * 64 * B_SUB_QUADS];   // [j_tile][k_sub][2048] = 64MB

// ==================== helpers ====================
__device__ __forceinline__ uint32_t smem_u32(const void* p) {
    uint32_t a;
    asm("{ .reg .u64 t; cvta.to.shared.u64 t, %1; cvt.u32.u64 %0, t; }" : "=r"(a) : "l"(p));
    return a;
}
#define CP16(dst, src) asm volatile("cp.async.cg.shared.global [%0], [%1], 16;" :: "r"(dst), "l"(src))
#define CP_COMMIT()    asm volatile("cp.async.commit_group;" ::: "memory")
#define CP_WAIT(n)     asm volatile("cp.async.wait_group %0;" :: "n"(n) : "memory")
#define PREF_L2(p)     asm volatile("prefetch.global.L2 [%0];" :: "l"(p))

#define MMA_F16(d, a, b)                                                         \
    asm volatile("mma.sync.aligned.m16n8k16.row.col.f32.f16.f16.f32 "            \
                 "{%0,%1,%2,%3}, {%4,%5,%6,%7}, {%8,%9}, {%0,%1,%2,%3};"         \
                 : "+f"((d)[0]), "+f"((d)[1]), "+f"((d)[2]), "+f"((d)[3])        \
                 : "r"((a)[0]), "r"((a)[1]), "r"((a)[2]), "r"((a)[3]),           \
                   "r"((b)[0]), "r"((b)[1]))

#define LDS128(r, addr)                                                          \
    asm volatile("ld.shared.v4.u32 {%0,%1,%2,%3}, [%4];"                         \
                 : "=r"((r)[0]), "=r"((r)[1]), "=r"((r)[2]), "=r"((r)[3]) : "r"(addr))

__device__ __forceinline__ uint32_t h2u(__half2 v) { return *(uint32_t*)&v; }

// ==================== fused prepass: A and W blocks co-scheduled ====================
// blockIdx.y & 1 == 0 -> A role (mt = y>>1), == 1 -> W role (jt = y>>1)
// blockIdx.x = k-sub-block (64)
__global__ __launch_bounds__(256) void prep_fused(const float* __restrict__ x,
                                                  const float* __restrict__ h,
                                                  const float* __restrict__ W) {
    __shared__ __align__(16) char buf[32768];
    const int kst = blockIdx.x;
    const int role = blockIdx.y & 1;
    const int idx  = blockIdx.y >> 1;   // mt or jt, [0,32)
    const int tid = threadIdx.x;

    if (role == 0) {
        // ---- A role: [x|h] -> fp16 fragment quads ----
        float* t = (float*)buf;           // [128][64]
        const int kg0 = kst * 64;
        const float* src = (kg0 < H_DIM) ? x + (size_t)(idx * 128) * H_DIM + kg0
                                         : h + (size_t)(idx * 128) * H_DIM + (kg0 - H_DIM);
#pragma unroll
        for (int j = 0; j < 8; j++) {
            const int i = tid + 256 * j;
            const int r = i >> 4, c4 = (i & 15) << 2;
            *(float4*)(t + r * 64 + c4) = *(const float4*)(src + (size_t)r * H_DIM + c4);
        }
        __syncthreads();
        uint4* outp = g_Ap + ((size_t)idx * 64 + kst) * A_SUB_QUADS;
#pragma unroll
        for (int j = 0; j < 4; j++) {
            const int w = tid + 256 * j;
            const int m2 = w >> 4, k2s = w & 15;
            const int k2 = k2s ^ ((m2 & 3) << 2);
            const int m  = ((m2 >> 3) << 4) + (m2 & 7);
            const int kb = ((k2 >> 2) << 4) + ((k2 & 3) << 1);
            uint4 q;
            q.x = h2u(__floats2half2_rn(t[m * 64 + kb],           t[m * 64 + kb + 1]));
            q.y = h2u(__floats2half2_rn(t[(m + 8) * 64 + kb],     t[(m + 8) * 64 + kb + 1]));
            q.z = h2u(__floats2half2_rn(t[m * 64 + kb + 8],       t[m * 64 + kb + 9]));
            q.w = h2u(__floats2half2_rn(t[(m + 8) * 64 + kb + 8], t[(m + 8) * 64 + kb + 9]));
            outp[w] = q;
        }
    } else {
        // ---- W role: -> fp16 fragment quads, 4-gate interleaved ----
        __half* th = (__half*)buf;        // [64][256]
#pragma unroll
        for (int j = 0; j < 16; j++) {
            const int i = tid + 256 * j;
            const int r = i >> 6, sc4 = (i & 63) << 2;
            const int g = sc4 >> 6, jl = sc4 & 63;
            float4 v = *(const float4*)(W + (size_t)(kst * 64 + r) * N4 + g * H_DIM + idx * 64 + jl);
            __half* d = th + r * 256 + sc4;
            d[0] = __float2half_rn(v.x); d[1] = __float2half_rn(v.y);
            d[2] = __float2half_rn(v.z); d[3] = __float2half_rn(v.w);
        }
        __syncthreads();
        uint4* outp = g_Wp + ((size_t)idx * 64 + kst) * B_SUB_QUADS;
#pragma unroll
        for (int j = 0; j < 8; j++) {
            const int w = tid + 256 * j;
            const int k2 = w >> 7, cn2s = w & 127;
            const int cn2 = cn2s ^ ((k2 & 3) << 1);
            const int r0 = ((k2 >> 2) << 4) + ((k2 & 3) << 1);
            const int n  = ((cn2 >> 5) << 6) + (((cn2 >> 3) & 3) << 3) + (cn2 & 7);
            const int g  = (n >> 3) & 3;
            const int jl = ((n >> 5) << 3) | (n & 7);
            const int gc = g * 64 + jl;
            uint4 q;
            q.x = h2u(__halves2half2(th[r0 * 256 + gc],           th[(r0 + 1) * 256 + gc]));
            q.y = h2u(__halves2half2(th[(r0 + 8) * 256 + gc],     th[(r0 + 9) * 256 + gc]));
            q.z = h2u(__halves2half2(th[r0 * 256 + gc + 8],       th[(r0 + 1) * 256 + gc + 8]));
            q.w = h2u(__halves2half2(th[(r0 + 8) * 256 + gc + 8], th[(r0 + 9) * 256 + gc + 8]));
            outp[w] = q;
        }
    }
}

extern __shared__ float smem[];

// ==================== fused GEMM + sLSTM kernel (persistent) ====================
__global__ __launch_bounds__(NTHREADS, 1)
void slstm_mma(const float* __restrict__ c_in, const float* __restrict__ n_in,
               const float* __restrict__ m_in, const float* __restrict__ bias,
               float* __restrict__ out)
{
    const int tid = threadIdx.x;
    const int wid = tid >> 5, lane = tid & 31;
    const int gID = lane >> 2, tg = lane & 3;
    const int warpM = wid >> 2, warpN = wid & 3;     // 2 x 4 warp grid, 64x64 tiles

    const uint32_t sbase = smem_u32(smem);
    const size_t plane = (size_t)B_DIM * H_DIM;

    // tile-invariant fragment addressing (bytes, within a 64-k sub-block)
    uint32_t aoff[4];
#pragma unroll
    for (int mt = 0; mt < 4; mt++)
        aoff[mt] = (uint32_t)(((warpM * 4 + mt) * 8 + gID) * 256);
    const uint32_t axr = (uint32_t)((gID & 3) << 2);
    uint32_t boffq[4];
#pragma unroll
    for (int ntp = 0; ntp < 4; ntp++)
        boffq[ntp] = (uint32_t)((((warpN * 32 + ntp * 8 + gID) ^ (tg << 1))
                                 + tg * 128) << 4);

    // stage copy: 24 x 16B chunks per thread
    auto load_stage = [&](int slot, const uint4* sa, const uint4* sb) {
        const uint32_t ab = sbase + (uint32_t)(slot * STG_BYTES);
#pragma unroll
        for (int i = 0; i < 8; i++) {
            const int c = tid + NTHREADS * i;
            CP16(ab + c * 16, sa + c);
        }
        const uint32_t bb = ab + A_ST_QUADS * 16;
#pragma unroll
        for (int i = 0; i < 16; i++) {
            const int c = tid + NTHREADS * i;
            CP16(bb + c * 16, sb + c);
        }
    };

    // double-buffered fragments
    uint32_t ar[2][4][4];
    uint32_t br[2][8][2];
    auto frag_load = [&](uint32_t St, int ks, int buf) {
        const int sub = ks >> 2, ksl = ks & 3;
        const uint32_t As = St + (uint32_t)(sub * (A_SUB_QUADS * 16));
        const uint32_t Bs = St + (uint32_t)(A_ST_QUADS * 16 + sub * (B_SUB_QUADS * 16));
        const uint32_t kpart = (uint32_t)(((ksl * 4 + tg) ^ axr) << 4);
#pragma unroll
        for (int mt = 0; mt < 4; mt++)
            LDS128(ar[buf][mt], As + aoff[mt] + kpart);
#pragma unroll
        for (int ntp = 0; ntp < 4; ntp++) {
            uint32_t t4[4];
            LDS128(t4, Bs + (uint32_t)(ksl * 8192) + boffq[ntp]);
            br[buf][ntp][0]     = t4[0];
            br[buf][ntp][1]     = t4[1];
            br[buf][ntp + 4][0] = t4[2];
            br[buf][ntp + 4][1] = t4[3];
        }
    };

    // prologue: stage 0 of first tile
    {
        const int t0 = blockIdx.x;
        load_stage(0, g_Ap + (size_t)(t0 & 31) * 64 * A_SUB_QUADS,
                      g_Wp + (size_t)(t0 >> 5) * 64 * B_SUB_QUADS);
        CP_COMMIT();
    }

    for (int tile = blockIdx.x; tile < NTILES; tile += GRID) {
        const int mtile = tile & 31;
        const int jt = tile >> 5;
        const int m0 = mtile * BM, jb = jt * BJ;
        const uint4* srcAbase = g_Ap + (size_t)mtile * 64 * A_SUB_QUADS;
        const uint4* srcBbase = g_Wp + (size_t)jt * 64 * B_SUB_QUADS;

        float acc[4][8][4];
#pragma unroll
        for (int a = 0; a < 4; a++)
#pragma unroll
            for (int b = 0; b < 8; b++)
#pragma unroll
                for (int c = 0; c < 4; c++) acc[a][b][c] = 0.f;

        for (int it = 0; it < NIT; ++it) {
            CP_WAIT(0);
            __syncthreads();

            const int nx = it + 1;
            if (nx < NIT)
                load_stage(nx & 1, srcAbase + (size_t)nx * A_ST_QUADS,
                                   srcBbase + (size_t)nx * B_ST_QUADS);
            CP_COMMIT();

            if (it == NIT - 1) {
                // prefetch epilogue state inputs to L2
#pragma unroll
                for (int mt = 0; mt < 4; mt++) {
#pragma unroll
                    for (int r2 = 0; r2 < 2; r2++) {
                        const int m = m0 + warpM * 64 + mt * 16 + gID + 8 * r2;
#pragma unroll
                        for (int q = 0; q < 2; q++) {
                            const size_t off = (size_t)m * H_DIM + jb
                                             + (2 * warpN + q) * 8 + 2 * tg;
                            PREF_L2(c_in + off);
                            PREF_L2(n_in + off);
                            PREF_L2(m_in + off);
                        }
                    }
                }
            }

            const uint32_t St = sbase + (uint32_t)((it & 1) * STG_BYTES);
            frag_load(St, 0, 0);
#pragma unroll
            for (int ks = 0; ks < 8; ks++) {
                const int cur = ks & 1;
                if (ks < 7) frag_load(St, ks + 1, cur ^ 1);
#pragma unroll
                for (int mt = 0; mt < 4; mt++)
#pragma unroll
                    for (int nt = 0; nt < 8; nt++)
                        MMA_F16(acc[mt][nt], ar[cur][mt], br[cur][nt]);
            }
        }

        // issue next tile's stage-0 copy before the epilogue (hides prologue)
        {
            const int tn = tile + GRID;
            if (tn < NTILES) {
                load_stage(0, g_Ap + (size_t)(tn & 31) * 64 * A_SUB_QUADS,
                              g_Wp + (size_t)(tn >> 5) * 64 * B_SUB_QUADS);
                CP_COMMIT();
            }
        }

        // ---- fused sLSTM epilogue (fast-math, streaming cache ops) ----
#pragma unroll
        for (int mt = 0; mt < 4; mt++) {
#pragma unroll
            for (int r2 = 0; r2 < 2; r2++) {
                const int m = m0 + warpM * 64 + mt * 16 + gID + 8 * r2;
#pragma unroll
                for (int q = 0; q < 2; q++) {
                    const int j = jb + (2 * warpN + q) * 8 + 2 * tg;
                    const size_t off = (size_t)m * H_DIM + j;
                    const float2 cv = __ldcs((const float2*)(c_in + off));
                    const float2 nv = __ldcs((const float2*)(n_in + off));
                    const float2 mv = __ldcs((const float2*)(m_in + off));
                    float2 ho, co, no, mo;
#pragma unroll
                    for (int e = 0; e < 2; e++) {
                        const float zt  = acc[mt][q * 4 + 0][r2 * 2 + e] + bias[j + e];
                        const float it_ = acc[mt][q * 4 + 1][r2 * 2 + e] + bias[H_DIM + j + e];
                        const float ft  = acc[mt][q * 4 + 2][r2 * 2 + e] + bias[2 * H_DIM + j + e];
                        const float ot  = acc[mt][q * 4 + 3][r2 * 2 + e] + bias[3 * H_DIM + j + e];

                        // tanh via exp
                        const float ez = __expf(-2.f * fabsf(zt));
                        const float tv = __fdividef(1.f - ez, 1.f + ez);
                        const float zv = (zt >= 0.f) ? tv : -tv;
                        // sigmoid(f) + log sigmoid(f)
                        const float ef = __expf(-fabsf(ft));
                        const float rf = __fdividef(1.f, 1.f + ef);
                        const float sf = (ft >= 0.f) ? rf : ef * rf;
                        const float logsig = fminf(ft, 0.f) - __logf(1.f + ef);
                        // sigmoid(o)
                        const float eo = __expf(-fabsf(ot));
                        const float ro = __fdividef(1.f, 1.f + eo);
                        const float so = (ot >= 0.f) ? ro : eo * ro;

                        const float m_old = e ? mv.y : mv.x;
                        const float mt_ = fmaxf(logsig + m_old, it_);
                        const float ip = __expf(it_ - mt_);
                        const float ct = sf * (e ? cv.y : cv.x) + ip * zv;
                        const float ntv = sf * (e ? nv.y : nv.x) + ip;
                        const float htv = so * __fdividef(ct, ntv);

                        *(e ? &ho.y : &ho.x) = htv;
                        *(e ? &co.y : &co.x) = ct;
                        *(e ? &no.y : &no.x) = ntv;
                        *(e ? &mo.y : &mo.x) = mt_;
                    }
                    __stcs((float2*)(out + off),             ho);
                    __stcs((float2*)(out + plane + off),     co);
                    __stcs((float2*)(out + 2 * plane + off), no);
                    __stcs((float2*)(out + 3 * plane + off), mo);
                }
            }
        }
    }
}

// ==================== host launch ====================
extern "C" void kernel_launch(void* const* d_in, const int* in_sizes, int n_in,
                              void* d_out, int out_size) {
    (void)in_sizes; (void)n_in; (void)out_size;
    const float* x    = (const float*)d_in[0];
    const float* h    = (const float*)d_in[1];
    const float* c    = (const float*)d_in[2];
    const float* n    = (const float*)d_in[3];
    const float* m    = (const float*)d_in[4];
    const float* W    = (const float*)d_in[5];
    const float* bias = (const float*)d_in[6];
    float* out = (float*)d_out;

    prep_fused<<<dim3(64, 64), 256>>>(x, h, W);

    cudaFuncSetAttribute(slstm_mma, cudaFuncAttributeMaxDynamicSharedMemorySize, SMEM_BYTES);
    slstm_mma<<<GRID, NTHREADS, SMEM_BYTES>>>(c, n, m, bias, out);
}